// round 15
// baseline (speedup 1.0000x reference)
#include <cuda_runtime.h>
#include <math.h>

// Problem constants
#define NB   64
#define SEQ  512
#define IN   256
#define HID  1024
#define ONN  256

// Kernel config
#define GRID 128          // 4 batch-groups x 32 j-tiles, all co-resident (<=148 SMs)
#define NTH  256
#define BT   16           // batches per CTA (per group)
#define JT   32           // j (hidden) per CTA
#define KW   128          // W_hh k-range per thread (HID / 8 warps)
#define KI   32           // W_ih k-range per thread (IN / 8 warps)
#define GCTA 32           // CTAs per batch-group

// 128 MB scratch for x_proj[t][b][j]
__device__ float g_xp[(size_t)SEQ * NB * HID];
__device__ unsigned g_cnt[4];        // one-shot barrier counters (zero-init at load)
__device__ unsigned g_gen[4];
__device__ unsigned g_cnt_all;
__device__ unsigned g_gen_all;
__device__ unsigned g_flag[4][32];   // per-CTA scan-step flags (monotonic across replays)

// packed fp32x2 FMA: c += a * b (elementwise on 2 floats)
__device__ __forceinline__ void ffma2(unsigned long long& c, unsigned long long a, unsigned long long b) {
    asm("fma.rn.f32x2 %0, %1, %2, %0;" : "+l"(c) : "l"(a), "l"(b));
}
__device__ __forceinline__ float red2(unsigned long long v) {
    float x, y;
    asm("mov.b64 {%0,%1}, %2;" : "=f"(x), "=f"(y) : "l"(v));
    return x + y;
}

// One-shot arrive-and-wait barrier (atomic counter + generation). Off hot path.
__device__ __forceinline__ void sw_barrier(unsigned* cnt, unsigned* gen, unsigned expected) {
    __syncthreads();
    if (threadIdx.x == 0) {
        unsigned g;
        asm volatile("ld.relaxed.gpu.global.u32 %0, [%1];" : "=r"(g) : "l"(gen));
        unsigned arrived;
        asm volatile("atom.acq_rel.gpu.global.add.u32 %0, [%1], %2;"
                     : "=r"(arrived) : "l"(cnt), "r"(1u));
        if (arrived == expected - 1) {
            asm volatile("st.relaxed.gpu.global.u32 [%0], %1;" :: "l"(cnt), "r"(0u));
            asm volatile("st.release.gpu.global.u32 [%0], %1;" :: "l"(gen), "r"(g + 1u));
        } else {
            unsigned cur;
            do {
                asm volatile("ld.acquire.gpu.global.u32 %0, [%1];" : "=r"(cur) : "l"(gen));
            } while (cur == g);
        }
    }
    __syncthreads();
}

__global__ void __launch_bounds__(NTH, 1)
rnn_kernel(const float* __restrict__ x,
           const float* __restrict__ w_ih,
           const float* __restrict__ w_hh,
           const float* __restrict__ bias,
           const float* __restrict__ fc_w,
           const float* __restrict__ fc_b,
           float* __restrict__ out)
{
    extern __shared__ float smem[];
    float* stage    = smem;             // BT*HID floats (64 KB); phase0 ping-pongs 2x32KB inside
    float* partials = smem + BT * HID;  // 2 * 8*512 floats (32 KB; phase0 uses both sets)

    const int tid  = threadIdx.x;
    const int w    = tid >> 5;
    const int lane = tid & 31;
    const int bt = blockIdx.x >> 5;   // 0..3  (batch group)
    const int jt = blockIdx.x & 31;   // 0..31 (j tile within group)
    const int b0 = bt * BT;
    const int j0 = jt * JT;
    const int j  = j0 + lane;         // this lane's output column

    float* hs = out + NB * ONN;       // hidden_states region [SEQ+1][NB][HID]

    // zero hs[0] rows owned by this group (group-local, so group barrier covers it)
    {
        float2* dst = (float2*)(hs + (size_t)b0 * HID);
        dst[jt * NTH + tid] = make_float2(0.f, 0.f);   // 32*256 float2 = 16*1024 floats
    }

    // ---------------- phase 0: x_proj = x @ W_ih^T (parallel over t; 2x unroll,
    //                  stage double-buffered so no trailing sync) ---------------
    {
        const int ki0 = w * KI;
        unsigned long long wih[KI / 2];
        {
            const ulonglong2* wrow = (const ulonglong2*)(w_ih + (size_t)j * IN + ki0);
            #pragma unroll
            for (int i = 0; i < KI / 4; i++) { ulonglong2 v = wrow[i]; wih[2*i] = v.x; wih[2*i+1] = v.y; }
        }
        for (int t = 0; t < SEQ; t += 2) {
            float* stg = stage + ((t >> 1) & 1) * (2 * BT * IN);
            for (int idx = tid; idx < 2 * BT * IN / 4; idx += NTH) {
                int s  = idx >> 10;
                int r  = idx & 1023;
                int b  = r >> 6;
                int i4 = r & 63;
                ((float4*)stg)[idx] =
                    ((const float4*)(x + ((size_t)(b0 + b) * SEQ + t + s) * IN))[i4];
            }
            __syncthreads();
            unsigned long long acc[2][BT];
            #pragma unroll
            for (int s = 0; s < 2; s++)
                #pragma unroll
                for (int b = 0; b < BT; b++) acc[s][b] = 0ull;
            #pragma unroll
            for (int kk = 0; kk < KI / 4; kk++) {
                #pragma unroll
                for (int s = 0; s < 2; s++) {
                    #pragma unroll
                    for (int b = 0; b < BT; b++) {
                        ulonglong2 hv = *(const ulonglong2*)&stg[s * BT * IN + b * IN + ki0 + kk * 4];
                        ffma2(acc[s][b], hv.x, wih[2*kk]);
                        ffma2(acc[s][b], hv.y, wih[2*kk+1]);
                    }
                }
            }
            #pragma unroll
            for (int s = 0; s < 2; s++)
                #pragma unroll
                for (int b = 0; b < BT; b++)
                    partials[s * 4096 + w * 512 + b * 32 + lane] = red2(acc[s][b]);
            __syncthreads();
            #pragma unroll
            for (int s = 0; s < 2; s++) {
                float* xpo = g_xp + (size_t)(t + s) * NB * HID;
                for (int r = tid; r < 512; r += NTH) {
                    float v = 0.f;
                    #pragma unroll
                    for (int ww = 0; ww < 8; ww++) v += partials[s * 4096 + ww * 512 + r];
                    xpo[(size_t)(b0 + (r >> 5)) * HID + j0 + (r & 31)] = v;
                }
            }
            // no trailing sync: stage double-buffered; next post-staging sync guards partials
        }
    }
    // group barrier: covers hs[0] zeros (xp is self-produced/self-consumed)
    sw_barrier(&g_cnt[bt], &g_gen[bt], GCTA);

    // ---------------- scan: h_{t+1} = tanh(xp + h W_hh^T + b) -----------------
    // Per-warp producer sync: warp w consumes h cols [128w,128w+128) produced by
    // CTAs jt'=4w..4w+3 of its group. Each warp polls those 4 flags, stages its
    // own 16x128 band (batched float4 loads, MLP=8), and proceeds independently
    // until the cross-warp reduce. h buffers are per-step distinct -> producers
    // may run ahead; no WAR. Flags monotonic -> replay-deterministic.
    {
        const int kw0 = w * KW;
        unsigned long long whh[KW / 2];   // 128 regs of register-resident W_hh
        {
            const ulonglong2* wrow = (const ulonglong2*)(w_hh + (size_t)j * HID + kw0);
            #pragma unroll
            for (int i = 0; i < KW / 4; i++) { ulonglong2 v = wrow[i]; whh[2*i] = v.x; whh[2*i+1] = v.y; }
        }
        const int   rb1   = tid >> 5;
        const int   rj    = tid & 31;
        const float biasv = bias[j0 + rj];

        // Epoch base: every flag gets exactly +SEQ per launch (0 at load), so our
        // own flag (written only by us) gives the grid-uniform base. Signed-diff
        // compares make it wraparound-safe.
        unsigned fbase;
        asm volatile("ld.relaxed.gpu.global.u32 %0, [%1];" : "=r"(fbase) : "l"(&g_flag[bt][jt]));

        const unsigned* pflag = &g_flag[bt][4 * w + (lane & 3)];  // this warp's 4 producers
        unsigned* myflag = &g_flag[bt][jt];

        const float* xp_base = g_xp + (size_t)(b0 + rb1) * HID + j0 + rj;      // + t*NB*HID
        float*       hw_base = hs + (size_t)(b0 + rb1) * HID + j0 + rj;        // + (t+1)*NB*HID

        for (int t = 0; t < SEQ; t++) {
            // prefetch this step's xp values (self-produced, immutable)
            const float* xp = xp_base + (size_t)t * NB * HID;
            float xpre0 = __ldg(xp);
            float xpre1 = __ldg(xp + (size_t)8 * HID);

            // ---- per-warp wait for the 4 producers of this warp's k-band ----
            if (t > 0) {
                const unsigned target = fbase + (unsigned)t;
                unsigned v;
                do {
                    asm volatile("ld.relaxed.gpu.global.u32 %0, [%1];"
                                 : "=r"(v) : "l"(pflag));
                } while (__any_sync(0xffffffffu, (int)(v - target) < 0));
                asm volatile("fence.acq_rel.gpu;" ::: "memory");
            }

            // ---- stage own 16x128 band: batched float4 loads (MLP=8) ----
            {
                const float* hsrc = hs + (size_t)t * NB * HID + (size_t)b0 * HID + kw0 + lane * 4;
                float*       sdst = stage + kw0 + lane * 4;
                float4 vb[8];
                #pragma unroll
                for (int r = 0; r < 8; r++) vb[r] = *(const float4*)(hsrc + (size_t)r * HID);
                #pragma unroll
                for (int r = 0; r < 8; r++) *(float4*)(sdst + (size_t)r * HID) = vb[r];
                #pragma unroll
                for (int r = 0; r < 8; r++) vb[r] = *(const float4*)(hsrc + (size_t)(8 + r) * HID);
                #pragma unroll
                for (int r = 0; r < 8; r++) *(float4*)(sdst + (size_t)(8 + r) * HID) = vb[r];
            }
            __syncwarp();    // cross-lane STS->LDS ordering within the warp

            // ---- FMA on own band (broadcast LDS, register-resident W) ----
            #pragma unroll 1
            for (int half = 0; half < 2; half++) {
                unsigned long long acc[8];
                #pragma unroll
                for (int b = 0; b < 8; b++) acc[b] = 0ull;
                const float* sb = stage + (half * 8) * HID + kw0;
                #pragma unroll
                for (int kk = 0; kk < KW / 4; kk++) {
                    #pragma unroll
                    for (int b = 0; b < 8; b++) {
                        ulonglong2 hv = *(const ulonglong2*)&sb[b * HID + kk * 4];
                        ffma2(acc[b], hv.x, whh[2*kk]);
                        ffma2(acc[b], hv.y, whh[2*kk+1]);
                    }
                }
                #pragma unroll
                for (int b = 0; b < 8; b++)
                    partials[w * 512 + (half * 8 + b) * 32 + lane] = red2(acc[b]);
            }
            __syncthreads();   // sync1: all warps' partials ready

            // ---- reduce + tanh + store h[t+1] ----
            {
                float* hdst = hw_base + (size_t)(t + 1) * NB * HID;
                #pragma unroll
                for (int u = 0; u < 2; u++) {
                    int r = tid + u * NTH;
                    float s = 0.f;
                    #pragma unroll
                    for (int ww = 0; ww < 8; ww++) s += partials[ww * 512 + r];
                    s += (u ? xpre1 : xpre0) + biasv;
                    hdst[(size_t)(u * 8) * HID] = tanhf(s);
                }
            }
            __syncthreads();   // sync2: h stores done (before release) + partials WAR guard

            if (tid == 0) {
                asm volatile("st.release.gpu.global.u32 [%0], %1;"
                             :: "l"(myflag), "r"(fbase + (unsigned)(t + 1)));
            }
        }
    }

    // full-grid barrier before fc (fc reads h rows across all groups)
    sw_barrier(&g_cnt_all, &g_gen_all, GRID);

    // ---------------- fc: out = h_S @ fc_w^T + fc_b ---------------------------
    {
        const float* hlast = hs + (size_t)SEQ * NB * HID;
        int gtid = blockIdx.x * NTH + tid;
        if (gtid < NB * ONN) {
            int b = gtid >> 8;
            int o = gtid & 255;
            const float4* hp = (const float4*)(hlast + (size_t)b * HID);
            const float4* wp = (const float4*)(fc_w + (size_t)o * HID);
            float s = fc_b[o];
            #pragma unroll 16
            for (int k = 0; k < HID / 4; k++) {
                float4 hv = hp[k], wv = wp[k];
                s += hv.x * wv.x + hv.y * wv.y + hv.z * wv.z + hv.w * wv.w;
            }
            out[gtid] = s;
        }
    }
}

extern "C" void kernel_launch(void* const* d_in, const int* in_sizes, int n_in,
                              void* d_out, int out_size) {
    const float* x    = (const float*)d_in[0];
    const float* w_ih = (const float*)d_in[1];
    const float* w_hh = (const float*)d_in[2];
    const float* bias = (const float*)d_in[3];
    const float* fc_w = (const float*)d_in[4];
    const float* fc_b = (const float*)d_in[5];
    float* out = (float*)d_out;

    int smem_bytes = (BT * HID + 2 * 8 * 512) * sizeof(float);  // 96 KB
    cudaFuncSetAttribute(rnn_kernel, cudaFuncAttributeMaxDynamicSharedMemorySize, smem_bytes);
    rnn_kernel<<<GRID, NTH, smem_bytes>>>(x, w_ih, w_hh, bias, fc_w, fc_b, out);
}

// round 16
// speedup vs baseline: 1.0078x; 1.0078x over previous
#include <cuda_runtime.h>
#include <math.h>

// Problem constants
#define NB   64
#define SEQ  512
#define IN   256
#define HID  1024
#define ONN  256

// Kernel config
#define GRID 128          // 4 batch-groups x 32 j-tiles, all co-resident (<=148 SMs)
#define NTH  256
#define BT   16           // batches per CTA (per group)
#define JT   32           // j (hidden) per CTA
#define KW   128          // W_hh k-range per thread (HID / 8 warps)
#define KI   32           // W_ih k-range per thread (IN / 8 warps)
#define GCTA 32           // CTAs per batch-group

// 128 MB scratch for x_proj[t][b][j]
__device__ float g_xp[(size_t)SEQ * NB * HID];
__device__ unsigned g_cnt[4];        // one-shot barrier counters (zero-init at load)
__device__ unsigned g_gen[4];
__device__ unsigned g_cnt_all;
__device__ unsigned g_gen_all;
__device__ unsigned g_flag[4][32];   // per-CTA scan-step flags (monotonic across replays)

// packed fp32x2 FMA: c += a * b (elementwise on 2 floats)
__device__ __forceinline__ void ffma2(unsigned long long& c, unsigned long long a, unsigned long long b) {
    asm("fma.rn.f32x2 %0, %1, %2, %0;" : "+l"(c) : "l"(a), "l"(b));
}
__device__ __forceinline__ float red2(unsigned long long v) {
    float x, y;
    asm("mov.b64 {%0,%1}, %2;" : "=f"(x), "=f"(y) : "l"(v));
    return x + y;
}

// One-shot arrive-and-wait barrier (atomic counter + generation). Off hot path.
__device__ __forceinline__ void sw_barrier(unsigned* cnt, unsigned* gen, unsigned expected) {
    __syncthreads();
    if (threadIdx.x == 0) {
        unsigned g;
        asm volatile("ld.relaxed.gpu.global.u32 %0, [%1];" : "=r"(g) : "l"(gen));
        unsigned arrived;
        asm volatile("atom.acq_rel.gpu.global.add.u32 %0, [%1], %2;"
                     : "=r"(arrived) : "l"(cnt), "r"(1u));
        if (arrived == expected - 1) {
            asm volatile("st.relaxed.gpu.global.u32 [%0], %1;" :: "l"(cnt), "r"(0u));
            asm volatile("st.release.gpu.global.u32 [%0], %1;" :: "l"(gen), "r"(g + 1u));
        } else {
            unsigned cur;
            do {
                asm volatile("ld.acquire.gpu.global.u32 %0, [%1];" : "=r"(cur) : "l"(gen));
            } while (cur == g);
        }
    }
    __syncthreads();
}

__global__ void __launch_bounds__(NTH, 1)
rnn_kernel(const float* __restrict__ x,
           const float* __restrict__ w_ih,
           const float* __restrict__ w_hh,
           const float* __restrict__ bias,
           const float* __restrict__ fc_w,
           const float* __restrict__ fc_b,
           float* __restrict__ out)
{
    extern __shared__ float smem[];
    float* stage    = smem;             // BT*HID floats (64 KB); phase0 ping-pongs 2x32KB inside
    float* partials = smem + BT * HID;  // 2 * 8*512 floats (32 KB; phase0 uses both sets)

    const int tid  = threadIdx.x;
    const int w    = tid >> 5;
    const int lane = tid & 31;
    const int bt = blockIdx.x >> 5;   // 0..3  (batch group)
    const int jt = blockIdx.x & 31;   // 0..31 (j tile within group)
    const int b0 = bt * BT;
    const int j0 = jt * JT;
    const int j  = j0 + lane;         // this lane's output column

    float* hs = out + NB * ONN;       // hidden_states region [SEQ+1][NB][HID]

    // zero hs[0] rows owned by this group (group-local, so group barrier covers it)
    {
        float2* dst = (float2*)(hs + (size_t)b0 * HID);
        dst[jt * NTH + tid] = make_float2(0.f, 0.f);   // 32*256 float2 = 16*1024 floats
    }

    // ---------------- phase 0: x_proj = x @ W_ih^T (parallel over t; 2x unroll,
    //                  stage double-buffered so no trailing sync) ---------------
    {
        const int ki0 = w * KI;
        unsigned long long wih[KI / 2];
        {
            const ulonglong2* wrow = (const ulonglong2*)(w_ih + (size_t)j * IN + ki0);
            #pragma unroll
            for (int i = 0; i < KI / 4; i++) { ulonglong2 v = wrow[i]; wih[2*i] = v.x; wih[2*i+1] = v.y; }
        }
        for (int t = 0; t < SEQ; t += 2) {
            float* stg = stage + ((t >> 1) & 1) * (2 * BT * IN);
            for (int idx = tid; idx < 2 * BT * IN / 4; idx += NTH) {
                int s  = idx >> 10;
                int r  = idx & 1023;
                int b  = r >> 6;
                int i4 = r & 63;
                ((float4*)stg)[idx] =
                    ((const float4*)(x + ((size_t)(b0 + b) * SEQ + t + s) * IN))[i4];
            }
            __syncthreads();
            unsigned long long acc[2][BT];
            #pragma unroll
            for (int s = 0; s < 2; s++)
                #pragma unroll
                for (int b = 0; b < BT; b++) acc[s][b] = 0ull;
            #pragma unroll
            for (int kk = 0; kk < KI / 4; kk++) {
                #pragma unroll
                for (int s = 0; s < 2; s++) {
                    #pragma unroll
                    for (int b = 0; b < BT; b++) {
                        ulonglong2 hv = *(const ulonglong2*)&stg[s * BT * IN + b * IN + ki0 + kk * 4];
                        ffma2(acc[s][b], hv.x, wih[2*kk]);
                        ffma2(acc[s][b], hv.y, wih[2*kk+1]);
                    }
                }
            }
            #pragma unroll
            for (int s = 0; s < 2; s++)
                #pragma unroll
                for (int b = 0; b < BT; b++)
                    partials[s * 4096 + w * 512 + b * 32 + lane] = red2(acc[s][b]);
            __syncthreads();
            #pragma unroll
            for (int s = 0; s < 2; s++) {
                float* xpo = g_xp + (size_t)(t + s) * NB * HID;
                for (int r = tid; r < 512; r += NTH) {
                    float v = 0.f;
                    #pragma unroll
                    for (int ww = 0; ww < 8; ww++) v += partials[s * 4096 + ww * 512 + r];
                    xpo[(size_t)(b0 + (r >> 5)) * HID + j0 + (r & 31)] = v;
                }
            }
            // no trailing sync: stage double-buffered; next post-staging sync guards partials
        }
    }
    // group barrier: covers hs[0] zeros (xp is self-produced/self-consumed)
    sw_barrier(&g_cnt[bt], &g_gen[bt], GCTA);

    // ---------------- scan: h_{t+1} = tanh(xp + h W_hh^T + b) -----------------
    // R5 (measured 7233us) structure: end-of-step flag-vector barrier (1 warp polls
    // all 32 group flags, coalesced). ONLY change vs R5: each warp stages its own
    // 16x128 h band with batched float4 loads (MLP=8) + __syncwarp, replacing the
    // serialized CTA-wide staging loop + __syncthreads.
    {
        const int kw0 = w * KW;
        unsigned long long whh[KW / 2];   // 128 regs of register-resident W_hh
        {
            const ulonglong2* wrow = (const ulonglong2*)(w_hh + (size_t)j * HID + kw0);
            #pragma unroll
            for (int i = 0; i < KW / 4; i++) { ulonglong2 v = wrow[i]; whh[2*i] = v.x; whh[2*i+1] = v.y; }
        }
        const int   rb1   = tid >> 5;
        const int   rj    = tid & 31;
        const float biasv = bias[j0 + rj];

        // Epoch base: every flag gets exactly +SEQ per launch (0 at load), so our
        // own flag (written only by us) gives the grid-uniform base. Signed-diff
        // compares make it wraparound-safe.
        unsigned fbase;
        asm volatile("ld.relaxed.gpu.global.u32 %0, [%1];" : "=r"(fbase) : "l"(&g_flag[bt][jt]));

        const float* xp_base = g_xp + (size_t)(b0 + rb1) * HID + j0 + rj;      // + t*NB*HID
        float*       hw_base = hs + (size_t)(b0 + rb1) * HID + j0 + rj;        // + (t+1)*NB*HID

        for (int t = 0; t < SEQ; t++) {
            // prefetch this step's xp values (self-produced, immutable)
            const float* xp = xp_base + (size_t)t * NB * HID;
            float xpre0 = __ldg(xp);
            float xpre1 = __ldg(xp + (size_t)8 * HID);

            // ---- stage own 16x128 band: batched float4 loads (MLP=8) ----
            // h_t fully visible: end-of-prev-step barrier (or phase-0 barrier at t=0).
            {
                const float* hsrc = hs + (size_t)t * NB * HID + (size_t)b0 * HID + kw0 + lane * 4;
                float*       sdst = stage + kw0 + lane * 4;
                float4 vb[8];
                #pragma unroll
                for (int r = 0; r < 8; r++) vb[r] = *(const float4*)(hsrc + (size_t)r * HID);
                #pragma unroll
                for (int r = 0; r < 8; r++) *(float4*)(sdst + (size_t)r * HID) = vb[r];
                #pragma unroll
                for (int r = 0; r < 8; r++) vb[r] = *(const float4*)(hsrc + (size_t)(8 + r) * HID);
                #pragma unroll
                for (int r = 0; r < 8; r++) *(float4*)(sdst + (size_t)(8 + r) * HID) = vb[r];
            }
            __syncwarp();    // warp consumes only its own band: no CTA-wide sync needed

            // ---- FMA on own band (broadcast LDS, register-resident W) ----
            #pragma unroll 1
            for (int half = 0; half < 2; half++) {
                unsigned long long acc[8];
                #pragma unroll
                for (int b = 0; b < 8; b++) acc[b] = 0ull;
                const float* sb = stage + (half * 8) * HID + kw0;
                #pragma unroll
                for (int kk = 0; kk < KW / 4; kk++) {
                    #pragma unroll
                    for (int b = 0; b < 8; b++) {
                        ulonglong2 hv = *(const ulonglong2*)&sb[b * HID + kk * 4];
                        ffma2(acc[b], hv.x, whh[2*kk]);
                        ffma2(acc[b], hv.y, whh[2*kk+1]);
                    }
                }
                #pragma unroll
                for (int b = 0; b < 8; b++)
                    partials[w * 512 + (half * 8 + b) * 32 + lane] = red2(acc[b]);
            }
            __syncthreads();   // sync1: all warps' partials ready

            // ---- reduce + tanh + store h[t+1] ----
            {
                float* hdst = hw_base + (size_t)(t + 1) * NB * HID;
                #pragma unroll
                for (int u = 0; u < 2; u++) {
                    int r = tid + u * NTH;
                    float s = 0.f;
                    #pragma unroll
                    for (int ww = 0; ww < 8; ww++) s += partials[ww * 512 + r];
                    s += (u ? xpre1 : xpre0) + biasv;
                    hdst[(size_t)(u * 8) * HID] = tanhf(s);
                }
            }

            // ---- flag-vector group barrier (parallel arrive, coalesced poll) ----
            // CTA-wide h-stores above are ordered into thread0's gpu-scope release
            // by this __syncthreads (CG grid.sync causality pattern).
            __syncthreads();
            const unsigned target = fbase + (unsigned)(t + 1);
            if (w == 0) {
                if (lane == 0) {
                    asm volatile("st.release.gpu.global.u32 [%0], %1;"
                                 :: "l"(&g_flag[bt][jt]), "r"(target));
                }
                unsigned v;
                do {
                    asm volatile("ld.relaxed.gpu.global.u32 %0, [%1];"
                                 : "=r"(v) : "l"(&g_flag[bt][lane]));
                } while (__any_sync(0xffffffffu, (int)(v - target) < 0));
                asm volatile("fence.acq_rel.gpu;" ::: "memory");
            }
            __syncthreads();
        }
    }

    // full-grid barrier before fc (fc reads h rows across all groups)
    sw_barrier(&g_cnt_all, &g_gen_all, GRID);

    // ---------------- fc: out = h_S @ fc_w^T + fc_b ---------------------------
    {
        const float* hlast = hs + (size_t)SEQ * NB * HID;
        int gtid = blockIdx.x * NTH + tid;
        if (gtid < NB * ONN) {
            int b = gtid >> 8;
            int o = gtid & 255;
            const float4* hp = (const float4*)(hlast + (size_t)b * HID);
            const float4* wp = (const float4*)(fc_w + (size_t)o * HID);
            float s = fc_b[o];
            #pragma unroll 16
            for (int k = 0; k < HID / 4; k++) {
                float4 hv = hp[k], wv = wp[k];
                s += hv.x * wv.x + hv.y * wv.y + hv.z * wv.z + hv.w * wv.w;
            }
            out[gtid] = s;
        }
    }
}

extern "C" void kernel_launch(void* const* d_in, const int* in_sizes, int n_in,
                              void* d_out, int out_size) {
    const float* x    = (const float*)d_in[0];
    const float* w_ih = (const float*)d_in[1];
    const float* w_hh = (const float*)d_in[2];
    const float* bias = (const float*)d_in[3];
    const float* fc_w = (const float*)d_in[4];
    const float* fc_b = (const float*)d_in[5];
    float* out = (float*)d_out;

    int smem_bytes = (BT * HID + 2 * 8 * 512) * sizeof(float);  // 96 KB
    cudaFuncSetAttribute(rnn_kernel, cudaFuncAttributeMaxDynamicSharedMemorySize, smem_bytes);
    rnn_kernel<<<GRID, NTH, smem_bytes>>>(x, w_ih, w_hh, bias, fc_w, fc_b, out);
}